// round 12
// baseline (speedup 1.0000x reference)
#include <cuda_runtime.h>
#include <cuda_bf16.h>
#include <cstdint>

typedef __nv_bfloat16 bf16;
typedef unsigned int u32;
typedef unsigned long long u64;

#define BB 8
#define SS 2048
#define DD 1024
#define MTOT (BB*SS)
#define NPERSIST 296

// ---------------- scratch pool ----------------
constexpr size_t SZ_ACT = (size_t)MTOT * DD * 2;
constexpr size_t SZ_P   = (size_t)BB * SS * SS * 2;
constexpr size_t SZ_W   = (size_t)DD * DD * 2;
constexpr size_t SZ_SC  = (size_t)BB * SS * SS * 4;
constexpr int N_ACT = 12;   // vis0/1 aud0/1 q0/1 k0/1 vwt0/1 h0/1
constexpr size_t O_P0 = (size_t)N_ACT * SZ_ACT;
constexpr size_t O_P1 = O_P0 + SZ_P;
constexpr size_t O_WT = O_P1 + SZ_P;
constexpr size_t O_SC = O_WT + 12 * SZ_W;
constexpr size_t O_BOP = O_SC + SZ_SC;
__device__ __align__(256) char g_pool[O_BOP + DD * 4];

// ---------------- helpers ----------------
__device__ __forceinline__ u32 smem_to_u32(const void* p) {
    u32 a;
    asm("{ .reg .u64 t; cvta.to.shared.u64 t, %1; cvt.u32.u64 %0, t; }" : "=r"(a) : "l"(p));
    return a;
}
#define SWZ64(off) ((off) ^ (((off) >> 3) & 0x30))

__device__ __forceinline__ void cp16(u32 s, const void* g) {
    asm volatile("cp.async.cg.shared.global [%0], [%1], 16;" :: "r"(s), "l"(g));
}
__device__ __forceinline__ void ldsm4(u32& r0, u32& r1, u32& r2, u32& r3, u32 a) {
    asm volatile("ldmatrix.sync.aligned.m8n8.x4.shared.b16 {%0,%1,%2,%3}, [%4];"
                 : "=r"(r0), "=r"(r1), "=r"(r2), "=r"(r3) : "r"(a));
}
__device__ __forceinline__ void mma16816(float* c, const u32* a, const u32* b) {
    asm("mma.sync.aligned.m16n8k16.row.col.f32.bf16.bf16.f32 "
        "{%0,%1,%2,%3},{%4,%5,%6,%7},{%8,%9},{%0,%1,%2,%3};"
        : "+f"(c[0]), "+f"(c[1]), "+f"(c[2]), "+f"(c[3])
        : "r"(a[0]), "r"(a[1]), "r"(a[2]), "r"(a[3]), "r"(b[0]), "r"(b[1]));
}

__device__ __forceinline__ void split2f(float v, bf16& a, bf16& b) {
    a = __float2bfloat16(v);
    b = __float2bfloat16(v - __bfloat162float(a));
}
__device__ __forceinline__ void st_bf2(bf16* p, bf16 a, bf16 b) {
    __nv_bfloat162 t; t.x = a; t.y = b;
    *reinterpret_cast<__nv_bfloat162*>(p) = t;
}

enum { EPI_BIAS = 1, EPI_RES = 2, EPI_RELU = 4 };
// NEMIT: 0 = fp32 C, 2 = bf16 split pair, 3 = fused dot-with-W2 -> atomicAdd out

struct GArgs {
    const bf16 *A0, *A1, *B0, *B1;
    float* C;
    bf16 *S0, *S1;
    const float *bias, *resid;
    const float* W2;
    float* outp;
    int K, lda, ldb, ldc;
    long sA, sB, sC;
    int nx, ny, nz;
};

// Persistent flat-pipelined split GEMM:
// C[M,N] = (A0+A1)@(B0+B1)^T via 3 split products, fp32 accum.
// 128x128 tiles, K-chunks of 32 bf16 (64B rows, SW64), 3-stage cp.async
// pipeline whose load cursor crosses tile boundaries (no drain per tile),
// 8 warps 2(M)x4(N), mma.sync m16n8k16. Grid <= 296 -> no wave quantization.
template<int EPI, int NEMIT>
__global__ void __launch_bounds__(256, 2) mma_gemm(const GArgs ga)
{
    extern __shared__ char dynsmem[];
    constexpr int NT = 4;
    constexpr int TILE = 8192;
    constexpr int NSTAGE = 3;

    const int tid = threadIdx.x, wid = tid >> 5, lane = tid & 31;
    const u32 tiles = (smem_to_u32(dynsmem) + 1023u) & ~1023u;
    const int wy = wid & 1, wx = wid >> 1;

    const int aRow = wy * 64 + (lane & 15);
    const int aKb  = (lane >> 4) * 16;
    const int bRow = wx * 32 + (lane & 7) + ((lane >> 4) & 1) * 8;
    const int bKb  = ((lane >> 3) & 1) * 16;

    const int ntiles = ga.nx * ga.ny * ga.nz;
    const int NC = ga.K >> 5;
    const int G = gridDim.x;
    if ((int)blockIdx.x >= ntiles) return;
    const int my_n = (ntiles - blockIdx.x + G - 1) / G;
    const long total_chunks = (long)my_n * NC;

    // ---- load cursor (runs ahead, crosses tile boundaries) ----
    int lt = blockIdx.x;
    int lc = 0;
    const bf16* lsrc[4];
    {
        const int txi = lt % ga.nx;
        const int rem = lt / ga.nx;
        const int tyi = rem % ga.ny;
        const long z = rem / ga.ny;
        lsrc[0] = ga.A0 + z * ga.sA + (long)(tyi * 128) * ga.lda;
        lsrc[1] = ga.A1 + z * ga.sA + (long)(tyi * 128) * ga.lda;
        lsrc[2] = ga.B0 + z * ga.sB + (long)(txi * 128) * ga.ldb;
        lsrc[3] = ga.B1 + z * ga.sB + (long)(txi * 128) * ga.ldb;
    }

    auto issue_load = [&](int buf) {
        const u32 sb = tiles + (u32)buf * (NT * TILE);
        const int k0 = lc << 5;
#pragma unroll
        for (int t = 0; t < NT; t++) {
            const int ld = (t < 2) ? ga.lda : ga.ldb;
#pragma unroll
            for (int u = 0; u < 2; u++) {
                const int i = u * 256 + tid;
                const int r = i >> 2, c16 = i & 3;
                cp16(sb + t * TILE + SWZ64((r << 6) + (c16 << 4)),
                     lsrc[t] + (long)r * ld + k0 + c16 * 8);
            }
        }
        asm volatile("cp.async.commit_group;" ::: "memory");
        if (++lc == NC) {
            lc = 0;
            lt += G;
            if (lt < ntiles) {
                const int txi = lt % ga.nx;
                const int rem = lt / ga.nx;
                const int tyi = rem % ga.ny;
                const long z = rem / ga.ny;
                lsrc[0] = ga.A0 + z * ga.sA + (long)(tyi * 128) * ga.lda;
                lsrc[1] = ga.A1 + z * ga.sA + (long)(tyi * 128) * ga.lda;
                lsrc[2] = ga.B0 + z * ga.sB + (long)(txi * 128) * ga.ldb;
                lsrc[3] = ga.B1 + z * ga.sB + (long)(txi * 128) * ga.ldb;
            }
        }
    };

    issue_load(0);
    if (total_chunks > 1) issue_load(1);

    int buf = 0, nbuf = 2;
    int ct = blockIdx.x;
    long flat = 0;

    for (int mt = 0; mt < my_n; ++mt, ct += G) {
        float acc[4][4][4];
#pragma unroll
        for (int i = 0; i < 4; i++)
#pragma unroll
            for (int j = 0; j < 4; j++)
#pragma unroll
                for (int r = 0; r < 4; r++) acc[i][j][r] = 0.f;

        for (int c = 0; c < NC; ++c, ++flat) {
            if (flat + 1 < total_chunks) {
                asm volatile("cp.async.wait_group 1;" ::: "memory");
            } else {
                asm volatile("cp.async.wait_group 0;" ::: "memory");
            }
            __syncthreads();
            if (flat + 2 < total_chunks) {
                issue_load(nbuf);
                if (++nbuf == NSTAGE) nbuf = 0;
            }

            const u32 sb = tiles + (u32)buf * (NT * TILE);
            if (++buf == NSTAGE) buf = 0;
#pragma unroll
            for (int kk = 0; kk < 2; kk++) {
                u32 bfr[2][2][4];
#pragma unroll
                for (int s = 0; s < 2; s++)
#pragma unroll
                    for (int nfp = 0; nfp < 2; nfp++) {
                        const u32 ad = sb + (2 + s) * TILE +
                            SWZ64((u32)((bRow + nfp * 16) * 64 + kk * 32 + bKb));
                        ldsm4(bfr[s][nfp][0], bfr[s][nfp][1], bfr[s][nfp][2], bfr[s][nfp][3], ad);
                    }
#pragma unroll
                for (int s = 0; s < 2; s++) {
#pragma unroll
                    for (int mf = 0; mf < 4; mf++) {
                        u32 af[4];
                        const u32 ad = sb + s * TILE +
                            SWZ64((u32)((aRow + mf * 16) * 64 + kk * 32 + aKb));
                        ldsm4(af[0], af[1], af[2], af[3], ad);
#pragma unroll
                        for (int nf = 0; nf < 4; nf++)
                            mma16816(acc[mf][nf], af, &bfr[0][nf >> 1][(nf & 1) * 2]);
                        if (s == 0) {
#pragma unroll
                            for (int nf = 0; nf < 4; nf++)
                                mma16816(acc[mf][nf], af, &bfr[1][nf >> 1][(nf & 1) * 2]);
                        }
                    }
                }
            }
        }

        // ---------------- epilogue for tile ct ----------------
        {
            const int txi = ct % ga.nx;
            const int rem = ct / ga.nx;
            const int tyi = rem % ga.ny;
            const long z = rem / ga.ny;
            const int m0 = tyi * 128, n0 = txi * 128;

            float* Cg = (NEMIT == 0) ? ga.C + z * ga.sC : nullptr;
            bf16 *S0g = nullptr, *S1g = nullptr;
            if (NEMIT == 2) { S0g = ga.S0 + z * ga.sC; S1g = ga.S1 + z * ga.sC; }
            const float* residZ = (EPI & EPI_RES) ? ga.resid + z * ga.sC : nullptr;

            const int erow = m0 + wy * 64 + (lane >> 2);
            const int ecol0 = n0 + wx * 32 + (lane & 3) * 2;

#pragma unroll
            for (int mf = 0; mf < 4; mf++) {
#pragma unroll
                for (int hh = 0; hh < 2; hh++) {
                    const long row = erow + mf * 16 + hh * 8;
                    const long rbase = row * ga.ldc;
                    float dot = 0.f;
#pragma unroll
                    for (int nf = 0; nf < 4; nf++) {
                        const int col = ecol0 + nf * 8;
                        float v0 = acc[mf][nf][hh * 2 + 0];
                        float v1 = acc[mf][nf][hh * 2 + 1];
                        if (EPI & EPI_BIAS) {
                            const float2 b = *reinterpret_cast<const float2*>(ga.bias + col);
                            v0 += b.x; v1 += b.y;
                        }
                        if (EPI & EPI_RES) {
                            const float2 r = *reinterpret_cast<const float2*>(residZ + rbase + col);
                            v0 += r.x; v1 += r.y;
                        }
                        if (EPI & EPI_RELU) { v0 = fmaxf(v0, 0.f); v1 = fmaxf(v1, 0.f); }
                        if (NEMIT == 0) {
                            *reinterpret_cast<float2*>(Cg + rbase + col) = make_float2(v0, v1);
                        } else if (NEMIT == 2) {
                            bf16 a0, a1, b0, b1;
                            split2f(v0, a0, b0);
                            split2f(v1, a1, b1);
                            st_bf2(S0g + rbase + col, a0, a1);
                            st_bf2(S1g + rbase + col, b0, b1);
                        } else {
                            const float2 w = *reinterpret_cast<const float2*>(ga.W2 + col);
                            dot = fmaf(v0, w.x, dot);
                            dot = fmaf(v1, w.y, dot);
                        }
                    }
                    if (NEMIT == 3) {
                        dot += __shfl_xor_sync(0xffffffffu, dot, 1);
                        dot += __shfl_xor_sync(0xffffffffu, dot, 2);
                        if ((lane & 3) == 0) atomicAdd(ga.outp + row, dot);
                    }
                }
            }
        }
    }
}

// ---------------- prep kernels ----------------
__global__ void __launch_bounds__(256) splitAct2(const float4* __restrict__ x,
                                                 bf16* s0, bf16* s1)
{
    const long i = (long)blockIdx.x * 256 + threadIdx.x;
    const float4 v = x[i];
    float f[4] = {v.x, v.y, v.z, v.w};
    bf16 a0[4], a1[4];
#pragma unroll
    for (int j = 0; j < 4; j++) split2f(f[j], a0[j], a1[j]);
    st_bf2(s0 + 4 * i, a0[0], a0[1]); st_bf2(s0 + 4 * i + 2, a0[2], a0[3]);
    st_bf2(s1 + 4 * i, a1[0], a1[1]); st_bf2(s1 + 4 * i + 2, a1[2], a1[3]);
}

__global__ void __launch_bounds__(256) wsplitT2(const float* __restrict__ W,
                                                bf16* t0, bf16* t1)
{
    __shared__ float tile[32][33];
    const int bk = blockIdx.x * 32, bn = blockIdx.y * 32;
    const int tx = threadIdx.x & 31, ty = threadIdx.x >> 5;
#pragma unroll
    for (int i = ty; i < 32; i += 8)
        tile[i][tx] = W[(long)(bk + i) * DD + bn + tx];
    __syncthreads();
#pragma unroll
    for (int i = ty; i < 32; i += 8) {
        const float v = tile[tx][i];
        const long o = (long)(bn + i) * DD + bk + tx;
        bf16 a, b;
        split2f(v, a, b);
        t0[o] = a; t1[o] = b;
    }
}

// bop[f] = bo[f] + sum_e bv[e] * Wo[e][f]
__global__ void __launch_bounds__(256) bvWo_kernel(const float* __restrict__ bv,
                                                   const float* __restrict__ Wo,
                                                   const float* __restrict__ bo,
                                                   float* __restrict__ bop)
{
    const int f = blockIdx.x * 256 + threadIdx.x;
    float s = bo[f];
#pragma unroll 4
    for (int e = 0; e < DD; e++) s += bv[e] * Wo[(long)e * DD + f];
    bop[f] = s;
}

__global__ void __launch_bounds__(256) softmax_split(const float4* __restrict__ sc4,
                                                     bf16* __restrict__ p0,
                                                     bf16* __restrict__ p1)
{
    __shared__ float red[8];
    __shared__ float bcast;
    const int t = threadIdx.x;
    const size_t base4 = (size_t)blockIdx.x * (SS / 4);
    float4 va = sc4[base4 + t];
    float4 vb = sc4[base4 + 256 + t];

    float m = fmaxf(fmaxf(fmaxf(va.x, va.y), fmaxf(va.z, va.w)),
                    fmaxf(fmaxf(vb.x, vb.y), fmaxf(vb.z, vb.w)));
#pragma unroll
    for (int o = 16; o; o >>= 1) m = fmaxf(m, __shfl_xor_sync(0xffffffffu, m, o));
    if ((t & 31) == 0) red[t >> 5] = m;
    __syncthreads();
    if (t == 0) {
        float mm = red[0];
#pragma unroll
        for (int i = 1; i < 8; i++) mm = fmaxf(mm, red[i]);
        bcast = mm;
    }
    __syncthreads();
    m = bcast;

    va.x = expf(va.x - m); va.y = expf(va.y - m);
    va.z = expf(va.z - m); va.w = expf(va.w - m);
    vb.x = expf(vb.x - m); vb.y = expf(vb.y - m);
    vb.z = expf(vb.z - m); vb.w = expf(vb.w - m);
    float s = va.x + va.y + va.z + va.w + vb.x + vb.y + vb.z + vb.w;
#pragma unroll
    for (int o = 16; o; o >>= 1) s += __shfl_xor_sync(0xffffffffu, s, o);
    __syncthreads();
    if ((t & 31) == 0) red[t >> 5] = s;
    __syncthreads();
    if (t == 0) {
        float ss = 0.f;
#pragma unroll
        for (int i = 0; i < 8; i++) ss += red[i];
        bcast = 1.f / ss;
    }
    __syncthreads();
    const float inv = bcast;

    const size_t eb = (size_t)blockIdx.x * SS;
    bf16 a0, b0, a1, b1;
    split2f(va.x * inv, a0, b0); split2f(va.y * inv, a1, b1);
    st_bf2(p0 + eb + 4 * t, a0, a1); st_bf2(p1 + eb + 4 * t, b0, b1);
    split2f(va.z * inv, a0, b0); split2f(va.w * inv, a1, b1);
    st_bf2(p0 + eb + 4 * t + 2, a0, a1); st_bf2(p1 + eb + 4 * t + 2, b0, b1);
    split2f(vb.x * inv, a0, b0); split2f(vb.y * inv, a1, b1);
    st_bf2(p0 + eb + 1024 + 4 * t, a0, a1); st_bf2(p1 + eb + 1024 + 4 * t, b0, b1);
    split2f(vb.z * inv, a0, b0); split2f(vb.w * inv, a1, b1);
    st_bf2(p0 + eb + 1024 + 4 * t + 2, a0, a1); st_bf2(p1 + eb + 1024 + 4 * t + 2, b0, b1);
}

__global__ void __launch_bounds__(256) init_out(float* __restrict__ out,
                                                const float* __restrict__ b2)
{
    out[blockIdx.x * 256 + threadIdx.x] = b2[0];
}

// ---------------- host ----------------
static inline int pgrid(int nx, int ny, int nz) {
    const int nt = nx * ny * nz;
    return nt < NPERSIST ? nt : NPERSIST;
}

extern "C" void kernel_launch(void* const* d_in, const int* in_sizes, int n_in,
                              void* d_out, int out_size)
{
    const float* visual = (const float*)d_in[0];
    const float* audio  = (const float*)d_in[1];
    const float* Wq = (const float*)d_in[2];  const float* bq = (const float*)d_in[3];
    const float* Wk = (const float*)d_in[4];  const float* bk = (const float*)d_in[5];
    const float* Wv = (const float*)d_in[6];  const float* bv = (const float*)d_in[7];
    const float* Wo = (const float*)d_in[8];  const float* bo = (const float*)d_in[9];
    const float* W1 = (const float*)d_in[10]; const float* b1 = (const float*)d_in[11];
    const float* W2 = (const float*)d_in[12]; const float* b2 = (const float*)d_in[13];
    float* out = (float*)d_out;

    char* pool;
    cudaGetSymbolAddress((void**)&pool, g_pool);
    auto act = [&](int i) { return (bf16*)(pool + (size_t)i * SZ_ACT); };
    bf16 *vis0 = act(0), *vis1 = act(1);
    bf16 *aud0 = act(2), *aud1 = act(3);
    bf16 *q0 = act(4),  *q1 = act(5);
    bf16 *k0 = act(6),  *k1 = act(7);
    bf16 *vwt0 = act(8), *vwt1 = act(9);
    bf16 *h0 = act(10),  *h1 = act(11);
    bf16 *p0 = (bf16*)(pool + O_P0), *p1 = (bf16*)(pool + O_P1);
    auto wt = [&](int i) { return (bf16*)(pool + O_WT + (size_t)i * SZ_W); };
    // 0,1 wqT  2,3 wkT  4,5 woT  6,7 w1T  8,9 wv(elementwise)  10,11 wfT
    float* sc = (float*)(pool + O_SC);
    float* bop = (float*)(pool + O_BOP);

    const int SMEM = 1024 + 3 * 4 * 8192;   // 99,328 -> 2 CTAs/SM
    cudaFuncSetAttribute((const void*)mma_gemm<EPI_BIAS,2>, cudaFuncAttributeMaxDynamicSharedMemorySize, SMEM);
    cudaFuncSetAttribute((const void*)mma_gemm<0,0>,        cudaFuncAttributeMaxDynamicSharedMemorySize, SMEM);
    cudaFuncSetAttribute((const void*)mma_gemm<0,2>,        cudaFuncAttributeMaxDynamicSharedMemorySize, SMEM);
    cudaFuncSetAttribute((const void*)mma_gemm<EPI_BIAS|EPI_RES,2>,  cudaFuncAttributeMaxDynamicSharedMemorySize, SMEM);
    cudaFuncSetAttribute((const void*)mma_gemm<EPI_BIAS|EPI_RELU,3>, cudaFuncAttributeMaxDynamicSharedMemorySize, SMEM);

    const int nb4 = (MTOT * DD) / 4 / 256;
    const int nbw4 = (DD * DD) / 4 / 256;
    const dim3 gw(DD / 32, DD / 32);
    GArgs a;

    splitAct2<<<nb4, 256>>>((const float4*)visual, vis0, vis1);   // 1
    splitAct2<<<nb4, 256>>>((const float4*)audio,  aud0, aud1);   // 2
    wsplitT2<<<gw, 256>>>(Wq, wt(0), wt(1));                      // 3

    // 4: Q = visual @ Wq + bq -> q splits   *** PROFILED ***
    a = {vis0, vis1, wt(0), wt(1), nullptr, q0, q1,
         bq, nullptr, nullptr, nullptr, DD, DD, DD, DD, 0, 0, 0, 8, 128, 1};
    mma_gemm<EPI_BIAS,2><<<pgrid(8,128,1), 256, SMEM>>>(a);

    wsplitT2<<<gw, 256>>>(Wk, wt(2), wt(3));                      // 5
    // 6: K = audio @ Wk + bk -> k splits
    a = {aud0, aud1, wt(2), wt(3), nullptr, k0, k1,
         bk, nullptr, nullptr, nullptr, DD, DD, DD, DD, 0, 0, 0, 8, 128, 1};
    mma_gemm<EPI_BIAS,2><<<pgrid(8,128,1), 256, SMEM>>>(a);

    splitAct2<<<nbw4, 256>>>((const float4*)Wv, wt(8), wt(9));    // 7
    wsplitT2<<<gw, 256>>>(Wo, wt(4), wt(5));                      // 8

    // 9: WfusedT[f][d] = sum_e WoT[f][e] * Wv[d][e] -> wfT splits
    a = {wt(4), wt(5), wt(8), wt(9), nullptr, wt(10), wt(11),
         nullptr, nullptr, nullptr, nullptr, DD, DD, DD, DD, 0, 0, 0, 8, 8, 1};
    mma_gemm<0,2><<<pgrid(8,8,1), 256, SMEM>>>(a);

    // 10: vwt[f][t] = sum_d WfusedT[f][d] * audio[t][d] -> vwt splits [DD x MTOT]
    a = {wt(10), wt(11), aud0, aud1, nullptr, vwt0, vwt1,
         nullptr, nullptr, nullptr, nullptr, DD, DD, DD, MTOT, 0, 0, 0, 128, 8, 1};
    mma_gemm<0,2><<<pgrid(128,8,1), 256, SMEM>>>(a);

    bvWo_kernel<<<DD / 256, 256>>>(bv, Wo, bo, bop);              // 11

    // 12: scores[b] = Q[b] @ K[b]^T -> fp32
    a = {q0, q1, k0, k1, sc, nullptr, nullptr,
         nullptr, nullptr, nullptr, nullptr, DD, DD, DD, SS,
         (long)SS * DD, (long)SS * DD, (long)SS * SS, 16, 16, BB};
    mma_gemm<0,0><<<pgrid(16,16,BB), 256, SMEM>>>(a);
    // 13: softmax -> p splits
    softmax_split<<<MTOT, 256>>>((const float4*)sc, p0, p1);
    // 14: h[b] = P[b] @ VW[b] + bo' + visual[b] -> h splits
    a = {p0, p1, vwt0, vwt1, nullptr, h0, h1,
         bop, visual, nullptr, nullptr, SS, SS, MTOT, DD,
         (long)SS * SS, (long)SS, (long)SS * DD, 8, 16, BB};
    mma_gemm<EPI_BIAS|EPI_RES,2><<<pgrid(8,16,BB), 256, SMEM>>>(a);

    wsplitT2<<<gw, 256>>>(W1, wt(6), wt(7));                      // 15
    init_out<<<MTOT / 256, 256>>>(out, b2);                       // 16
    // 17: x = relu(h @ W1 + b1); out += x . W2 (fused)
    a = {h0, h1, wt(6), wt(7), nullptr, nullptr, nullptr,
         b1, nullptr, W2, out, DD, DD, DD, DD, 0, 0, 0, 8, 128, 1};
    mma_gemm<EPI_BIAS|EPI_RELU,3><<<pgrid(8,128,1), 256, SMEM>>>(a);
}

// round 15
// speedup vs baseline: 1.1658x; 1.1658x over previous
#include <cuda_runtime.h>
#include <cuda_bf16.h>
#include <cstdint>

typedef __nv_bfloat16 bf16;
typedef unsigned int u32;
typedef unsigned long long u64;

#define BB 8
#define SS 2048
#define DD 1024
#define MTOT (BB*SS)

// ---------------- scratch pool ----------------
constexpr size_t SZ_ACT = (size_t)MTOT * DD * 2;
constexpr size_t SZ_P   = (size_t)BB * SS * SS * 2;
constexpr size_t SZ_W   = (size_t)DD * DD * 2;
constexpr size_t SZ_SC  = (size_t)BB * SS * SS * 4;
constexpr int N_ACT = 12;   // vis0/1 aud0/1 q0/1 k0/1 vwt0/1 h0/1
constexpr size_t O_P0 = (size_t)N_ACT * SZ_ACT;
constexpr size_t O_P1 = O_P0 + SZ_P;
constexpr size_t O_WT = O_P1 + SZ_P;
constexpr size_t O_SC = O_WT + 12 * SZ_W;
constexpr size_t O_BOP = O_SC + SZ_SC;
__device__ __align__(256) char g_pool[O_BOP + DD * 4];

// ---------------- helpers ----------------
__device__ __forceinline__ u32 smem_to_u32(const void* p) {
    u32 a;
    asm("{ .reg .u64 t; cvta.to.shared.u64 t, %1; cvt.u32.u64 %0, t; }" : "=r"(a) : "l"(p));
    return a;
}
#define SWZ64(off) ((off) ^ (((off) >> 3) & 0x30))

__device__ __forceinline__ void cp16(u32 s, const void* g) {
    asm volatile("cp.async.cg.shared.global [%0], [%1], 16;" :: "r"(s), "l"(g));
}
__device__ __forceinline__ void ldsm4(u32& r0, u32& r1, u32& r2, u32& r3, u32 a) {
    asm volatile("ldmatrix.sync.aligned.m8n8.x4.shared.b16 {%0,%1,%2,%3}, [%4];"
                 : "=r"(r0), "=r"(r1), "=r"(r2), "=r"(r3) : "r"(a));
}
__device__ __forceinline__ void mma16816(float* c, const u32* a, const u32* b) {
    asm("mma.sync.aligned.m16n8k16.row.col.f32.bf16.bf16.f32 "
        "{%0,%1,%2,%3},{%4,%5,%6,%7},{%8,%9},{%0,%1,%2,%3};"
        : "+f"(c[0]), "+f"(c[1]), "+f"(c[2]), "+f"(c[3])
        : "r"(a[0]), "r"(a[1]), "r"(a[2]), "r"(a[3]), "r"(b[0]), "r"(b[1]));
}

__device__ __forceinline__ void split2f(float v, bf16& a, bf16& b) {
    a = __float2bfloat16(v);
    b = __float2bfloat16(v - __bfloat162float(a));
}
__device__ __forceinline__ void st_bf2(bf16* p, bf16 a, bf16 b) {
    __nv_bfloat162 t; t.x = a; t.y = b;
    *reinterpret_cast<__nv_bfloat162*>(p) = t;
}

enum { EPI_BIAS = 1, EPI_RES = 2, EPI_RELU = 4 };
// NEMIT: 0 = fp32 C, 2 = bf16 split pair, 3 = fused dot-with-W2 -> atomicAdd out

struct GArgs {
    const bf16 *A0, *A1, *B0, *B1;
    float* C;
    bf16 *S0, *S1;
    const float *bias, *biasB;   // biasB: per-z bias for merged launches (nullptr -> use bias)
    const float* resid;
    const float* W2;
    float* outp;
    int K, lda, ldb, ldc;
    long sA, sB, sC;
};

// C[M,N] = (A0+A1)[M,K] @ (B0+B1)[N,K]^T via 3 split products, fp32 accum.
// Block 128x128, K-chunks of 32 bf16 (64B rows, SW64), 3-stage cp.async
// pipeline (96KB -> 2 CTAs/SM), 8 warps 2(M)x4(N), mma.sync m16n8k16.
template<int EPI, int NEMIT>
__global__ void __launch_bounds__(256, 2) mma_gemm(const GArgs ga)
{
    extern __shared__ char dynsmem[];
    constexpr int NT = 4;
    constexpr int TILE = 8192;
    constexpr int NSTAGE = 3;

    const int tid = threadIdx.x, wid = tid >> 5, lane = tid & 31;
    const u32 tiles = (smem_to_u32(dynsmem) + 1023u) & ~1023u;
    const long z = blockIdx.z;
    const int m0 = blockIdx.y * 128, n0 = blockIdx.x * 128;

    const bf16* src[NT];
    src[0] = ga.A0 + z * ga.sA + (long)m0 * ga.lda;
    src[1] = ga.A1 + z * ga.sA + (long)m0 * ga.lda;
    src[2] = ga.B0 + z * ga.sB + (long)n0 * ga.ldb;
    src[3] = ga.B1 + z * ga.sB + (long)n0 * ga.ldb;

    const int wy = wid & 1, wx = wid >> 1;

    float acc[4][4][4];
#pragma unroll
    for (int i = 0; i < 4; i++)
#pragma unroll
        for (int j = 0; j < 4; j++)
#pragma unroll
            for (int r = 0; r < 4; r++) acc[i][j][r] = 0.f;

    const int aRow = wy * 64 + (lane & 15);
    const int aKb  = (lane >> 4) * 16;
    const int bRow = wx * 32 + (lane & 7) + ((lane >> 4) & 1) * 8;
    const int bKb  = ((lane >> 3) & 1) * 16;

    auto load_chunk = [&](int k0, int buf) {
        const u32 sb = tiles + (u32)buf * (NT * TILE);
#pragma unroll
        for (int t = 0; t < NT; t++) {
            const int ld = (t < 2) ? ga.lda : ga.ldb;
#pragma unroll
            for (int u = 0; u < 2; u++) {
                const int i = u * 256 + tid;
                const int r = i >> 2, c16 = i & 3;
                cp16(sb + t * TILE + SWZ64((r << 6) + (c16 << 4)),
                     src[t] + (long)r * ld + k0 + c16 * 8);
            }
        }
        asm volatile("cp.async.commit_group;" ::: "memory");
    };

    const int NC = ga.K >> 5;
    load_chunk(0, 0);
    if (NC > 1) load_chunk(32, 1);

    int buf = 0, nbuf = 2;
    for (int c = 0; c < NC; ++c) {
        if (c + 1 < NC) {
            asm volatile("cp.async.wait_group 1;" ::: "memory");
        } else {
            asm volatile("cp.async.wait_group 0;" ::: "memory");
        }
        __syncthreads();
        if (c + 2 < NC) {
            load_chunk((c + 2) << 5, nbuf);
            if (++nbuf == NSTAGE) nbuf = 0;
        }

        const u32 sb = tiles + (u32)buf * (NT * TILE);
        if (++buf == NSTAGE) buf = 0;
#pragma unroll
        for (int kk = 0; kk < 2; kk++) {
            u32 bfr[2][2][4];
#pragma unroll
            for (int s = 0; s < 2; s++)
#pragma unroll
                for (int nfp = 0; nfp < 2; nfp++) {
                    const u32 ad = sb + (2 + s) * TILE +
                        SWZ64((u32)((bRow + nfp * 16) * 64 + kk * 32 + bKb));
                    ldsm4(bfr[s][nfp][0], bfr[s][nfp][1], bfr[s][nfp][2], bfr[s][nfp][3], ad);
                }
#pragma unroll
            for (int s = 0; s < 2; s++) {
#pragma unroll
                for (int mf = 0; mf < 4; mf++) {
                    u32 af[4];
                    const u32 ad = sb + s * TILE +
                        SWZ64((u32)((aRow + mf * 16) * 64 + kk * 32 + aKb));
                    ldsm4(af[0], af[1], af[2], af[3], ad);
#pragma unroll
                    for (int nf = 0; nf < 4; nf++)
                        mma16816(acc[mf][nf], af, &bfr[0][nf >> 1][(nf & 1) * 2]);
                    if (s == 0) {
#pragma unroll
                        for (int nf = 0; nf < 4; nf++)
                            mma16816(acc[mf][nf], af, &bfr[1][nf >> 1][(nf & 1) * 2]);
                    }
                }
            }
        }
    }

    // ---------------- epilogue from registers ----------------
    {
        float* Cg = (NEMIT == 0) ? ga.C + z * ga.sC : nullptr;
        bf16 *S0g = nullptr, *S1g = nullptr;
        if (NEMIT == 2) { S0g = ga.S0 + z * ga.sC; S1g = ga.S1 + z * ga.sC; }
        const float* residZ = (EPI & EPI_RES) ? ga.resid + z * ga.sC : nullptr;
        // per-z bias: use biasB for z>0 ONLY when provided (merged launches)
        const float* bz = (z != 0 && ga.biasB) ? ga.biasB : ga.bias;

        const int erow = m0 + wy * 64 + (lane >> 2);
        const int ecol0 = n0 + wx * 32 + (lane & 3) * 2;

#pragma unroll
        for (int mf = 0; mf < 4; mf++) {
#pragma unroll
            for (int hh = 0; hh < 2; hh++) {
                const long row = erow + mf * 16 + hh * 8;
                const long rbase = row * ga.ldc;
                float dot = 0.f;
#pragma unroll
                for (int nf = 0; nf < 4; nf++) {
                    const int col = ecol0 + nf * 8;
                    float v0 = acc[mf][nf][hh * 2 + 0];
                    float v1 = acc[mf][nf][hh * 2 + 1];
                    if (EPI & EPI_BIAS) {
                        const float2 b = *reinterpret_cast<const float2*>(bz + col);
                        v0 += b.x; v1 += b.y;
                    }
                    if (EPI & EPI_RES) {
                        const float2 r = *reinterpret_cast<const float2*>(residZ + rbase + col);
                        v0 += r.x; v1 += r.y;
                    }
                    if (EPI & EPI_RELU) { v0 = fmaxf(v0, 0.f); v1 = fmaxf(v1, 0.f); }
                    if (NEMIT == 0) {
                        *reinterpret_cast<float2*>(Cg + rbase + col) = make_float2(v0, v1);
                    } else if (NEMIT == 2) {
                        bf16 a0, a1, b0, b1;
                        split2f(v0, a0, b0);
                        split2f(v1, a1, b1);
                        st_bf2(S0g + rbase + col, a0, a1);
                        st_bf2(S1g + rbase + col, b0, b1);
                    } else {
                        const float2 w = *reinterpret_cast<const float2*>(ga.W2 + col);
                        dot = fmaf(v0, w.x, dot);
                        dot = fmaf(v1, w.y, dot);
                    }
                }
                if (NEMIT == 3) {
                    dot += __shfl_xor_sync(0xffffffffu, dot, 1);
                    dot += __shfl_xor_sync(0xffffffffu, dot, 2);
                    if ((lane & 3) == 0) atomicAdd(ga.outp + row, dot);
                }
            }
        }
    }
}

// ---------------- prep kernels ----------------
__global__ void __launch_bounds__(256) splitAct2(const float4* __restrict__ x,
                                                 bf16* s0, bf16* s1)
{
    const long i = (long)blockIdx.x * 256 + threadIdx.x;
    const float4 v = x[i];
    float f[4] = {v.x, v.y, v.z, v.w};
    bf16 a0[4], a1[4];
#pragma unroll
    for (int j = 0; j < 4; j++) split2f(f[j], a0[j], a1[j]);
    st_bf2(s0 + 4 * i, a0[0], a0[1]); st_bf2(s0 + 4 * i + 2, a0[2], a0[3]);
    st_bf2(s1 + 4 * i, a1[0], a1[1]); st_bf2(s1 + 4 * i + 2, a1[2], a1[3]);
}

// transpose+split one matrix (z selects source/dest pair)
__global__ void __launch_bounds__(256) wsplitT2z(const float* __restrict__ Wa,
                                                 const float* __restrict__ Wb,
                                                 bf16* a0, bf16* a1,
                                                 bf16* b0, bf16* b1)
{
    __shared__ float tile[32][33];
    const float* W = blockIdx.z ? Wb : Wa;
    bf16* t0 = blockIdx.z ? b0 : a0;
    bf16* t1 = blockIdx.z ? b1 : a1;
    const int bk = blockIdx.x * 32, bn = blockIdx.y * 32;
    const int tx = threadIdx.x & 31, ty = threadIdx.x >> 5;
#pragma unroll
    for (int i = ty; i < 32; i += 8)
        tile[i][tx] = W[(long)(bk + i) * DD + bn + tx];
    __syncthreads();
#pragma unroll
    for (int i = ty; i < 32; i += 8) {
        const float v = tile[tx][i];
        const long o = (long)(bn + i) * DD + bk + tx;
        bf16 a, b;
        split2f(v, a, b);
        t0[o] = a; t1[o] = b;
    }
}

// bop[f] = bo[f] + sum_e bv[e] * Wo[e][f]
__global__ void __launch_bounds__(256) bvWo_kernel(const float* __restrict__ bv,
                                                   const float* __restrict__ Wo,
                                                   const float* __restrict__ bo,
                                                   float* __restrict__ bop)
{
    const int f = blockIdx.x * 256 + threadIdx.x;
    float s = bo[f];
#pragma unroll 4
    for (int e = 0; e < DD; e++) s += bv[e] * Wo[(long)e * DD + f];
    bop[f] = s;
}

__global__ void __launch_bounds__(256) softmax_split(const float4* __restrict__ sc4,
                                                     bf16* __restrict__ p0,
                                                     bf16* __restrict__ p1)
{
    __shared__ float red[8];
    __shared__ float bcast;
    const int t = threadIdx.x;
    const size_t base4 = (size_t)blockIdx.x * (SS / 4);
    float4 va = sc4[base4 + t];
    float4 vb = sc4[base4 + 256 + t];

    float m = fmaxf(fmaxf(fmaxf(va.x, va.y), fmaxf(va.z, va.w)),
                    fmaxf(fmaxf(vb.x, vb.y), fmaxf(vb.z, vb.w)));
#pragma unroll
    for (int o = 16; o; o >>= 1) m = fmaxf(m, __shfl_xor_sync(0xffffffffu, m, o));
    if ((t & 31) == 0) red[t >> 5] = m;
    __syncthreads();
    if (t == 0) {
        float mm = red[0];
#pragma unroll
        for (int i = 1; i < 8; i++) mm = fmaxf(mm, red[i]);
        bcast = mm;
    }
    __syncthreads();
    m = bcast;

    va.x = expf(va.x - m); va.y = expf(va.y - m);
    va.z = expf(va.z - m); va.w = expf(va.w - m);
    vb.x = expf(vb.x - m); vb.y = expf(vb.y - m);
    vb.z = expf(vb.z - m); vb.w = expf(vb.w - m);
    float s = va.x + va.y + va.z + va.w + vb.x + vb.y + vb.z + vb.w;
#pragma unroll
    for (int o = 16; o; o >>= 1) s += __shfl_xor_sync(0xffffffffu, s, o);
    __syncthreads();
    if ((t & 31) == 0) red[t >> 5] = s;
    __syncthreads();
    if (t == 0) {
        float ss = 0.f;
#pragma unroll
        for (int i = 0; i < 8; i++) ss += red[i];
        bcast = 1.f / ss;
    }
    __syncthreads();
    const float inv = bcast;

    const size_t eb = (size_t)blockIdx.x * SS;
    bf16 a0, b0, a1, b1;
    split2f(va.x * inv, a0, b0); split2f(va.y * inv, a1, b1);
    st_bf2(p0 + eb + 4 * t, a0, a1); st_bf2(p1 + eb + 4 * t, b0, b1);
    split2f(va.z * inv, a0, b0); split2f(va.w * inv, a1, b1);
    st_bf2(p0 + eb + 4 * t + 2, a0, a1); st_bf2(p1 + eb + 4 * t + 2, b0, b1);
    split2f(vb.x * inv, a0, b0); split2f(vb.y * inv, a1, b1);
    st_bf2(p0 + eb + 1024 + 4 * t, a0, a1); st_bf2(p1 + eb + 1024 + 4 * t, b0, b1);
    split2f(vb.z * inv, a0, b0); split2f(vb.w * inv, a1, b1);
    st_bf2(p0 + eb + 1024 + 4 * t + 2, a0, a1); st_bf2(p1 + eb + 1024 + 4 * t + 2, b0, b1);
}

__global__ void __launch_bounds__(256) init_out(float* __restrict__ out,
                                                const float* __restrict__ b2)
{
    out[blockIdx.x * 256 + threadIdx.x] = b2[0];
}

// ---------------- host ----------------
extern "C" void kernel_launch(void* const* d_in, const int* in_sizes, int n_in,
                              void* d_out, int out_size)
{
    const float* visual = (const float*)d_in[0];
    const float* audio  = (const float*)d_in[1];
    const float* Wq = (const float*)d_in[2];  const float* bq = (const float*)d_in[3];
    const float* Wk = (const float*)d_in[4];  const float* bk = (const float*)d_in[5];
    const float* Wv = (const float*)d_in[6];  const float* bv = (const float*)d_in[7];
    const float* Wo = (const float*)d_in[8];  const float* bo = (const float*)d_in[9];
    const float* W1 = (const float*)d_in[10]; const float* b1 = (const float*)d_in[11];
    const float* W2 = (const float*)d_in[12]; const float* b2 = (const float*)d_in[13];
    float* out = (float*)d_out;

    char* pool;
    cudaGetSymbolAddress((void**)&pool, g_pool);
    auto act = [&](int i) { return (bf16*)(pool + (size_t)i * SZ_ACT); };
    bf16 *vis0 = act(0), *vis1 = act(1);
    bf16 *aud0 = act(2), *aud1 = act(3);
    bf16 *q0 = act(4),  *q1 = act(5);
    bf16 *k0 = act(6),  *k1 = act(7);      // contiguous after q: z-stride works
    bf16 *vwt0 = act(8), *vwt1 = act(9);
    bf16 *h0 = act(10),  *h1 = act(11);
    bf16 *p0 = (bf16*)(pool + O_P0), *p1 = (bf16*)(pool + O_P1);
    auto wt = [&](int i) { return (bf16*)(pool + O_WT + (size_t)i * SZ_W); };
    // 0,1 wqT  2,3 wkT  4,5 woT  6,7 w1T  8,9 wv(elementwise)  10,11 wfT
    float* sc = (float*)(pool + O_SC);
    float* bop = (float*)(pool + O_BOP);

    const long ACT_Z = 2L * MTOT * DD;   // 2 slots, in elements
    const long W_Z   = 2L * DD * DD;

    const int SMEM = 1024 + 3 * 4 * 8192;   // 99,328 -> 2 CTAs/SM
    cudaFuncSetAttribute((const void*)mma_gemm<EPI_BIAS,2>, cudaFuncAttributeMaxDynamicSharedMemorySize, SMEM);
    cudaFuncSetAttribute((const void*)mma_gemm<0,0>,        cudaFuncAttributeMaxDynamicSharedMemorySize, SMEM);
    cudaFuncSetAttribute((const void*)mma_gemm<0,2>,        cudaFuncAttributeMaxDynamicSharedMemorySize, SMEM);
    cudaFuncSetAttribute((const void*)mma_gemm<EPI_BIAS|EPI_RES,2>,  cudaFuncAttributeMaxDynamicSharedMemorySize, SMEM);
    cudaFuncSetAttribute((const void*)mma_gemm<EPI_BIAS|EPI_RELU,3>, cudaFuncAttributeMaxDynamicSharedMemorySize, SMEM);

    const int nb4 = (MTOT * DD) / 4 / 256;
    const int nbw4 = (DD * DD) / 4 / 256;
    GArgs a;

    splitAct2<<<nb4, 256>>>((const float4*)visual, vis0, vis1);           // 1
    splitAct2<<<nb4, 256>>>((const float4*)audio,  aud0, aud1);           // 2
    wsplitT2z<<<dim3(DD/32, DD/32, 2), 256>>>(Wq, Wk,
                                              wt(0), wt(1), wt(2), wt(3)); // 3

    // 4: merged Q/K projection, z=0: Q=vis@Wq+bq, z=1: K=aud@Wk+bk  *** PROFILED ***
    a = {vis0, vis1, wt(0), wt(1), nullptr, q0, q1,
         bq, bk, nullptr, nullptr, nullptr, DD, DD, DD, DD,
         ACT_Z, W_Z, ACT_Z};
    mma_gemm<EPI_BIAS,2><<<dim3(8, 128, 2), 256, SMEM>>>(a);

    splitAct2<<<nbw4, 256>>>((const float4*)Wv, wt(8), wt(9));            // 5
    wsplitT2z<<<dim3(DD/32, DD/32, 1), 256>>>(Wo, Wo,
                                              wt(4), wt(5), wt(4), wt(5)); // 6

    // 7: WfusedT[f][d] = sum_e WoT[f][e] * Wv[d][e] -> wfT splits
    a = {wt(4), wt(5), wt(8), wt(9), nullptr, wt(10), wt(11),
         nullptr, nullptr, nullptr, nullptr, nullptr, DD, DD, DD, DD, 0, 0, 0};
    mma_gemm<0,2><<<dim3(8, 8, 1), 256, SMEM>>>(a);

    // 8: vwt[f][t] = sum_d WfusedT[f][d] * audio[t][d] -> vwt splits [DD x MTOT]
    a = {wt(10), wt(11), aud0, aud1, nullptr, vwt0, vwt1,
         nullptr, nullptr, nullptr, nullptr, nullptr, DD, DD, DD, MTOT, 0, 0, 0};
    mma_gemm<0,2><<<dim3(128, 8, 1), 256, SMEM>>>(a);

    bvWo_kernel<<<DD / 256, 256>>>(bv, Wo, bo, bop);                      // 9

    // 10: scores[b] = Q[b] @ K[b]^T -> fp32
    a = {q0, q1, k0, k1, sc, nullptr, nullptr,
         nullptr, nullptr, nullptr, nullptr, nullptr, DD, DD, DD, SS,
         (long)SS * DD, (long)SS * DD, (long)SS * SS};
    mma_gemm<0,0><<<dim3(16, 16, BB), 256, SMEM>>>(a);
    // 11: softmax -> p splits
    softmax_split<<<MTOT, 256>>>((const float4*)sc, p0, p1);
    // 12: h[b] = P[b] @ VW[b] + bo' + visual[b] -> h splits (biasB=nullptr -> bop for all z)
    a = {p0, p1, vwt0, vwt1, nullptr, h0, h1,
         bop, nullptr, visual, nullptr, nullptr, SS, SS, MTOT, DD,
         (long)SS * SS, (long)SS, (long)SS * DD};
    mma_gemm<EPI_BIAS|EPI_RES,2><<<dim3(8, 16, BB), 256, SMEM>>>(a);

    wsplitT2z<<<dim3(DD/32, DD/32, 1), 256>>>(W1, W1,
                                              wt(6), wt(7), wt(6), wt(7)); // 13
    init_out<<<MTOT / 256, 256>>>(out, b2);                               // 14
    // 15: x = relu(h @ W1 + b1); out += x . W2 (fused)
    a = {h0, h1, wt(6), wt(7), nullptr, nullptr, nullptr,
         b1, nullptr, nullptr, W2, out, DD, DD, DD, DD, 0, 0, 0};
    mma_gemm<EPI_BIAS|EPI_RELU,3><<<dim3(8, 128, 1), 256, SMEM>>>(a);
}

// round 16
// speedup vs baseline: 1.1903x; 1.0211x over previous
#include <cuda_runtime.h>
#include <cuda_bf16.h>
#include <cstdint>

typedef __nv_bfloat16 bf16;
typedef unsigned int u32;
typedef unsigned long long u64;

#define BB 8
#define SS 2048
#define DD 1024
#define MTOT (BB*SS)

// ---------------- scratch pool ----------------
constexpr size_t SZ_ACT = (size_t)MTOT * DD * 2;
constexpr size_t SZ_P   = (size_t)BB * SS * SS * 2;
constexpr size_t SZ_W   = (size_t)DD * DD * 2;
constexpr size_t SZ_SC  = (size_t)BB * SS * SS * 4;
constexpr int N_ACT = 12;   // vis0/1 aud0/1 q0/1 k0/1 vwt0/1 h0/1
constexpr size_t O_P0 = (size_t)N_ACT * SZ_ACT;
constexpr size_t O_P1 = O_P0 + SZ_P;
constexpr size_t O_WT = O_P1 + SZ_P;
constexpr size_t O_SC = O_WT + 12 * SZ_W;
constexpr size_t O_BOP = O_SC + SZ_SC;
__device__ __align__(256) char g_pool[O_BOP + DD * 4];

// ---------------- helpers ----------------
__device__ __forceinline__ u32 smem_to_u32(const void* p) {
    u32 a;
    asm("{ .reg .u64 t; cvta.to.shared.u64 t, %1; cvt.u32.u64 %0, t; }" : "=r"(a) : "l"(p));
    return a;
}
#define SWZ64(off) ((off) ^ (((off) >> 3) & 0x30))

__device__ __forceinline__ void cp16(u32 s, const void* g) {
    asm volatile("cp.async.cg.shared.global [%0], [%1], 16;" :: "r"(s), "l"(g));
}
__device__ __forceinline__ void ldsm4(u32& r0, u32& r1, u32& r2, u32& r3, u32 a) {
    asm volatile("ldmatrix.sync.aligned.m8n8.x4.shared.b16 {%0,%1,%2,%3}, [%4];"
                 : "=r"(r0), "=r"(r1), "=r"(r2), "=r"(r3) : "r"(a));
}
__device__ __forceinline__ void mma16816(float* c, const u32* a, const u32* b) {
    asm("mma.sync.aligned.m16n8k16.row.col.f32.bf16.bf16.f32 "
        "{%0,%1,%2,%3},{%4,%5,%6,%7},{%8,%9},{%0,%1,%2,%3};"
        : "+f"(c[0]), "+f"(c[1]), "+f"(c[2]), "+f"(c[3])
        : "r"(a[0]), "r"(a[1]), "r"(a[2]), "r"(a[3]), "r"(b[0]), "r"(b[1]));
}

__device__ __forceinline__ void split2f(float v, bf16& a, bf16& b) {
    a = __float2bfloat16(v);
    b = __float2bfloat16(v - __bfloat162float(a));
}
__device__ __forceinline__ void st_bf2(bf16* p, bf16 a, bf16 b) {
    __nv_bfloat162 t; t.x = a; t.y = b;
    *reinterpret_cast<__nv_bfloat162*>(p) = t;
}

enum { EPI_BIAS = 1, EPI_RES = 2, EPI_RELU = 4 };
// NEMIT: 0 = fp32 C, 2 = bf16 split pair, 3 = fused dot-with-W2 -> atomicAdd out

struct GArgs {
    const bf16 *A0, *A1, *B0, *B1;
    float* C;
    bf16 *S0, *S1;
    const float *bias, *biasB;   // biasB: per-z bias for merged launches (nullptr -> use bias)
    const float* resid;
    const float* W2;
    float* outp;
    int K, lda, ldb, ldc;
    long sA, sB, sC;
};

// C[M,N] = (A0+A1)[M,K] @ (B0+B1)[N,K]^T via 3 split products, fp32 accum.
// Block 128x128, K-chunks of 32 bf16 (64B rows, SW64), 3-stage cp.async
// pipeline (96KB -> 2 CTAs/SM), 8 warps 2(M)x4(N), mma.sync m16n8k16.
// All 12 LDSM per kk-step hoisted ahead of the 48 MMAs (single latency exposure).
template<int EPI, int NEMIT>
__global__ void __launch_bounds__(256, 2) mma_gemm(const GArgs ga)
{
    extern __shared__ char dynsmem[];
    constexpr int NT = 4;
    constexpr int TILE = 8192;
    constexpr int NSTAGE = 3;

    const int tid = threadIdx.x, wid = tid >> 5, lane = tid & 31;
    const u32 tiles = (smem_to_u32(dynsmem) + 1023u) & ~1023u;
    const long z = blockIdx.z;
    const int m0 = blockIdx.y * 128, n0 = blockIdx.x * 128;

    const bf16* src[NT];
    src[0] = ga.A0 + z * ga.sA + (long)m0 * ga.lda;
    src[1] = ga.A1 + z * ga.sA + (long)m0 * ga.lda;
    src[2] = ga.B0 + z * ga.sB + (long)n0 * ga.ldb;
    src[3] = ga.B1 + z * ga.sB + (long)n0 * ga.ldb;

    const int wy = wid & 1, wx = wid >> 1;

    float acc[4][4][4];
#pragma unroll
    for (int i = 0; i < 4; i++)
#pragma unroll
        for (int j = 0; j < 4; j++)
#pragma unroll
            for (int r = 0; r < 4; r++) acc[i][j][r] = 0.f;

    const int aRow = wy * 64 + (lane & 15);
    const int aKb  = (lane >> 4) * 16;
    const int bRow = wx * 32 + (lane & 7) + ((lane >> 4) & 1) * 8;
    const int bKb  = ((lane >> 3) & 1) * 16;

    auto load_chunk = [&](int k0, int buf) {
        const u32 sb = tiles + (u32)buf * (NT * TILE);
#pragma unroll
        for (int t = 0; t < NT; t++) {
            const int ld = (t < 2) ? ga.lda : ga.ldb;
#pragma unroll
            for (int u = 0; u < 2; u++) {
                const int i = u * 256 + tid;
                const int r = i >> 2, c16 = i & 3;
                cp16(sb + t * TILE + SWZ64((r << 6) + (c16 << 4)),
                     src[t] + (long)r * ld + k0 + c16 * 8);
            }
        }
        asm volatile("cp.async.commit_group;" ::: "memory");
    };

    const int NC = ga.K >> 5;
    load_chunk(0, 0);
    if (NC > 1) load_chunk(32, 1);

    int buf = 0, nbuf = 2;
    for (int c = 0; c < NC; ++c) {
        if (c + 1 < NC) {
            asm volatile("cp.async.wait_group 1;" ::: "memory");
        } else {
            asm volatile("cp.async.wait_group 0;" ::: "memory");
        }
        __syncthreads();
        if (c + 2 < NC) {
            load_chunk((c + 2) << 5, nbuf);
            if (++nbuf == NSTAGE) nbuf = 0;
        }

        const u32 sb = tiles + (u32)buf * (NT * TILE);
        if (++buf == NSTAGE) buf = 0;
#pragma unroll
        for (int kk = 0; kk < 2; kk++) {
            // ---- hoist: issue ALL 12 LDSM back-to-back ----
            u32 bfr[2][2][4];
#pragma unroll
            for (int s = 0; s < 2; s++)
#pragma unroll
                for (int nfp = 0; nfp < 2; nfp++) {
                    const u32 ad = sb + (2 + s) * TILE +
                        SWZ64((u32)((bRow + nfp * 16) * 64 + kk * 32 + bKb));
                    ldsm4(bfr[s][nfp][0], bfr[s][nfp][1], bfr[s][nfp][2], bfr[s][nfp][3], ad);
                }
            u32 afr[2][4][4];
#pragma unroll
            for (int s = 0; s < 2; s++)
#pragma unroll
                for (int mf = 0; mf < 4; mf++) {
                    const u32 ad = sb + s * TILE +
                        SWZ64((u32)((aRow + mf * 16) * 64 + kk * 32 + aKb));
                    ldsm4(afr[s][mf][0], afr[s][mf][1], afr[s][mf][2], afr[s][mf][3], ad);
                }
            // ---- then all 48 MMAs ----
#pragma unroll
            for (int mf = 0; mf < 4; mf++) {
#pragma unroll
                for (int nf = 0; nf < 4; nf++)
                    mma16816(acc[mf][nf], afr[0][mf], &bfr[0][nf >> 1][(nf & 1) * 2]);
#pragma unroll
                for (int nf = 0; nf < 4; nf++)
                    mma16816(acc[mf][nf], afr[0][mf], &bfr[1][nf >> 1][(nf & 1) * 2]);
#pragma unroll
                for (int nf = 0; nf < 4; nf++)
                    mma16816(acc[mf][nf], afr[1][mf], &bfr[0][nf >> 1][(nf & 1) * 2]);
            }
        }
    }

    // ---------------- epilogue from registers ----------------
    {
        float* Cg = (NEMIT == 0) ? ga.C + z * ga.sC : nullptr;
        bf16 *S0g = nullptr, *S1g = nullptr;
        if (NEMIT == 2) { S0g = ga.S0 + z * ga.sC; S1g = ga.S1 + z * ga.sC; }
        const float* residZ = (EPI & EPI_RES) ? ga.resid + z * ga.sC : nullptr;
        const float* bz = (z != 0 && ga.biasB) ? ga.biasB : ga.bias;

        const int erow = m0 + wy * 64 + (lane >> 2);
        const int ecol0 = n0 + wx * 32 + (lane & 3) * 2;

#pragma unroll
        for (int mf = 0; mf < 4; mf++) {
#pragma unroll
            for (int hh = 0; hh < 2; hh++) {
                const long row = erow + mf * 16 + hh * 8;
                const long rbase = row * ga.ldc;
                float dot = 0.f;
#pragma unroll
                for (int nf = 0; nf < 4; nf++) {
                    const int col = ecol0 + nf * 8;
                    float v0 = acc[mf][nf][hh * 2 + 0];
                    float v1 = acc[mf][nf][hh * 2 + 1];
                    if (EPI & EPI_BIAS) {
                        const float2 b = *reinterpret_cast<const float2*>(bz + col);
                        v0 += b.x; v1 += b.y;
                    }
                    if (EPI & EPI_RES) {
                        const float2 r = *reinterpret_cast<const float2*>(residZ + rbase + col);
                        v0 += r.x; v1 += r.y;
                    }
                    if (EPI & EPI_RELU) { v0 = fmaxf(v0, 0.f); v1 = fmaxf(v1, 0.f); }
                    if (NEMIT == 0) {
                        *reinterpret_cast<float2*>(Cg + rbase + col) = make_float2(v0, v1);
                    } else if (NEMIT == 2) {
                        bf16 a0, a1, b0, b1;
                        split2f(v0, a0, b0);
                        split2f(v1, a1, b1);
                        st_bf2(S0g + rbase + col, a0, a1);
                        st_bf2(S1g + rbase + col, b0, b1);
                    } else {
                        const float2 w = *reinterpret_cast<const float2*>(ga.W2 + col);
                        dot = fmaf(v0, w.x, dot);
                        dot = fmaf(v1, w.y, dot);
                    }
                }
                if (NEMIT == 3) {
                    dot += __shfl_xor_sync(0xffffffffu, dot, 1);
                    dot += __shfl_xor_sync(0xffffffffu, dot, 2);
                    if ((lane & 3) == 0) atomicAdd(ga.outp + row, dot);
                }
            }
        }
    }
}

// ---------------- prep kernels ----------------
__global__ void __launch_bounds__(256) splitAct2(const float4* __restrict__ x,
                                                 bf16* s0, bf16* s1)
{
    const long i = (long)blockIdx.x * 256 + threadIdx.x;
    const float4 v = x[i];
    float f[4] = {v.x, v.y, v.z, v.w};
    bf16 a0[4], a1[4];
#pragma unroll
    for (int j = 0; j < 4; j++) split2f(f[j], a0[j], a1[j]);
    st_bf2(s0 + 4 * i, a0[0], a0[1]); st_bf2(s0 + 4 * i + 2, a0[2], a0[3]);
    st_bf2(s1 + 4 * i, a1[0], a1[1]); st_bf2(s1 + 4 * i + 2, a1[2], a1[3]);
}

// transpose+split one matrix (z selects source/dest pair)
__global__ void __launch_bounds__(256) wsplitT2z(const float* __restrict__ Wa,
                                                 const float* __restrict__ Wb,
                                                 bf16* a0, bf16* a1,
                                                 bf16* b0, bf16* b1)
{
    __shared__ float tile[32][33];
    const float* W = blockIdx.z ? Wb : Wa;
    bf16* t0 = blockIdx.z ? b0 : a0;
    bf16* t1 = blockIdx.z ? b1 : a1;
    const int bk = blockIdx.x * 32, bn = blockIdx.y * 32;
    const int tx = threadIdx.x & 31, ty = threadIdx.x >> 5;
#pragma unroll
    for (int i = ty; i < 32; i += 8)
        tile[i][tx] = W[(long)(bk + i) * DD + bn + tx];
    __syncthreads();
#pragma unroll
    for (int i = ty; i < 32; i += 8) {
        const float v = tile[tx][i];
        const long o = (long)(bn + i) * DD + bk + tx;
        bf16 a, b;
        split2f(v, a, b);
        t0[o] = a; t1[o] = b;
    }
}

// bop[f] = bo[f] + sum_e bv[e] * Wo[e][f]
__global__ void __launch_bounds__(256) bvWo_kernel(const float* __restrict__ bv,
                                                   const float* __restrict__ Wo,
                                                   const float* __restrict__ bo,
                                                   float* __restrict__ bop)
{
    const int f = blockIdx.x * 256 + threadIdx.x;
    float s = bo[f];
#pragma unroll 4
    for (int e = 0; e < DD; e++) s += bv[e] * Wo[(long)e * DD + f];
    bop[f] = s;
}

__global__ void __launch_bounds__(256) softmax_split(const float4* __restrict__ sc4,
                                                     bf16* __restrict__ p0,
                                                     bf16* __restrict__ p1)
{
    __shared__ float red[8];
    __shared__ float bcast;
    const int t = threadIdx.x;
    const size_t base4 = (size_t)blockIdx.x * (SS / 4);
    float4 va = sc4[base4 + t];
    float4 vb = sc4[base4 + 256 + t];

    float m = fmaxf(fmaxf(fmaxf(va.x, va.y), fmaxf(va.z, va.w)),
                    fmaxf(fmaxf(vb.x, vb.y), fmaxf(vb.z, vb.w)));
#pragma unroll
    for (int o = 16; o; o >>= 1) m = fmaxf(m, __shfl_xor_sync(0xffffffffu, m, o));
    if ((t & 31) == 0) red[t >> 5] = m;
    __syncthreads();
    if (t == 0) {
        float mm = red[0];
#pragma unroll
        for (int i = 1; i < 8; i++) mm = fmaxf(mm, red[i]);
        bcast = mm;
    }
    __syncthreads();
    m = bcast;

    va.x = expf(va.x - m); va.y = expf(va.y - m);
    va.z = expf(va.z - m); va.w = expf(va.w - m);
    vb.x = expf(vb.x - m); vb.y = expf(vb.y - m);
    vb.z = expf(vb.z - m); vb.w = expf(vb.w - m);
    float s = va.x + va.y + va.z + va.w + vb.x + vb.y + vb.z + vb.w;
#pragma unroll
    for (int o = 16; o; o >>= 1) s += __shfl_xor_sync(0xffffffffu, s, o);
    __syncthreads();
    if ((t & 31) == 0) red[t >> 5] = s;
    __syncthreads();
    if (t == 0) {
        float ss = 0.f;
#pragma unroll
        for (int i = 0; i < 8; i++) ss += red[i];
        bcast = 1.f / ss;
    }
    __syncthreads();
    const float inv = bcast;

    const size_t eb = (size_t)blockIdx.x * SS;
    bf16 a0, b0, a1, b1;
    split2f(va.x * inv, a0, b0); split2f(va.y * inv, a1, b1);
    st_bf2(p0 + eb + 4 * t, a0, a1); st_bf2(p1 + eb + 4 * t, b0, b1);
    split2f(va.z * inv, a0, b0); split2f(va.w * inv, a1, b1);
    st_bf2(p0 + eb + 4 * t + 2, a0, a1); st_bf2(p1 + eb + 4 * t + 2, b0, b1);
    split2f(vb.x * inv, a0, b0); split2f(vb.y * inv, a1, b1);
    st_bf2(p0 + eb + 1024 + 4 * t, a0, a1); st_bf2(p1 + eb + 1024 + 4 * t, b0, b1);
    split2f(vb.z * inv, a0, b0); split2f(vb.w * inv, a1, b1);
    st_bf2(p0 + eb + 1024 + 4 * t + 2, a0, a1); st_bf2(p1 + eb + 1024 + 4 * t + 2, b0, b1);
}

__global__ void __launch_bounds__(256) init_out(float* __restrict__ out,
                                                const float* __restrict__ b2)
{
    out[blockIdx.x * 256 + threadIdx.x] = b2[0];
}

// ---------------- host ----------------
extern "C" void kernel_launch(void* const* d_in, const int* in_sizes, int n_in,
                              void* d_out, int out_size)
{
    const float* visual = (const float*)d_in[0];
    const float* audio  = (const float*)d_in[1];
    const float* Wq = (const float*)d_in[2];  const float* bq = (const float*)d_in[3];
    const float* Wk = (const float*)d_in[4];  const float* bk = (const float*)d_in[5];
    const float* Wv = (const float*)d_in[6];  const float* bv = (const float*)d_in[7];
    const float* Wo = (const float*)d_in[8];  const float* bo = (const float*)d_in[9];
    const float* W1 = (const float*)d_in[10]; const float* b1 = (const float*)d_in[11];
    const float* W2 = (const float*)d_in[12]; const float* b2 = (const float*)d_in[13];
    float* out = (float*)d_out;

    char* pool;
    cudaGetSymbolAddress((void**)&pool, g_pool);
    auto act = [&](int i) { return (bf16*)(pool + (size_t)i * SZ_ACT); };
    bf16 *vis0 = act(0), *vis1 = act(1);
    bf16 *aud0 = act(2), *aud1 = act(3);
    bf16 *q0 = act(4),  *q1 = act(5);
    bf16 *k0 = act(6),  *k1 = act(7);      // contiguous after q: z-stride works
    bf16 *vwt0 = act(8), *vwt1 = act(9);
    bf16 *h0 = act(10),  *h1 = act(11);
    bf16 *p0 = (bf16*)(pool + O_P0), *p1 = (bf16*)(pool + O_P1);
    auto wt = [&](int i) { return (bf16*)(pool + O_WT + (size_t)i * SZ_W); };
    // 0,1 wqT  2,3 wkT  4,5 woT  6,7 w1T  8,9 wv(elementwise)  10,11 wfT
    float* sc = (float*)(pool + O_SC);
    float* bop = (float*)(pool + O_BOP);

    const long ACT_Z = 2L * MTOT * DD;   // 2 slots, in elements
    const long W_Z   = 2L * DD * DD;

    const int SMEM = 1024 + 3 * 4 * 8192;   // 99,328 -> 2 CTAs/SM
    cudaFuncSetAttribute((const void*)mma_gemm<EPI_BIAS,2>, cudaFuncAttributeMaxDynamicSharedMemorySize, SMEM);
    cudaFuncSetAttribute((const void*)mma_gemm<0,0>,        cudaFuncAttributeMaxDynamicSharedMemorySize, SMEM);
    cudaFuncSetAttribute((const void*)mma_gemm<0,2>,        cudaFuncAttributeMaxDynamicSharedMemorySize, SMEM);
    cudaFuncSetAttribute((const void*)mma_gemm<EPI_BIAS|EPI_RES,2>,  cudaFuncAttributeMaxDynamicSharedMemorySize, SMEM);
    cudaFuncSetAttribute((const void*)mma_gemm<EPI_BIAS|EPI_RELU,3>, cudaFuncAttributeMaxDynamicSharedMemorySize, SMEM);

    const int nb4 = (MTOT * DD) / 4 / 256;
    const int nbw4 = (DD * DD) / 4 / 256;
    GArgs a;

    splitAct2<<<nb4, 256>>>((const float4*)visual, vis0, vis1);           // 1
    splitAct2<<<nb4, 256>>>((const float4*)audio,  aud0, aud1);           // 2
    wsplitT2z<<<dim3(DD/32, DD/32, 2), 256>>>(Wq, Wk,
                                              wt(0), wt(1), wt(2), wt(3)); // 3

    // 4: merged Q/K projection, z=0: Q=vis@Wq+bq, z=1: K=aud@Wk+bk  *** PROFILED ***
    a = {vis0, vis1, wt(0), wt(1), nullptr, q0, q1,
         bq, bk, nullptr, nullptr, nullptr, DD, DD, DD, DD,
         ACT_Z, W_Z, ACT_Z};
    mma_gemm<EPI_BIAS,2><<<dim3(8, 128, 2), 256, SMEM>>>(a);

    splitAct2<<<nbw4, 256>>>((const float4*)Wv, wt(8), wt(9));            // 5
    wsplitT2z<<<dim3(DD/32, DD/32, 1), 256>>>(Wo, Wo,
                                              wt(4), wt(5), wt(4), wt(5)); // 6

    // 7: WfusedT[f][d] = sum_e WoT[f][e] * Wv[d][e] -> wfT splits
    a = {wt(4), wt(5), wt(8), wt(9), nullptr, wt(10), wt(11),
         nullptr, nullptr, nullptr, nullptr, nullptr, DD, DD, DD, DD, 0, 0, 0};
    mma_gemm<0,2><<<dim3(8, 8, 1), 256, SMEM>>>(a);

    // 8: vwt[f][t] = sum_d WfusedT[f][d] * audio[t][d] -> vwt splits [DD x MTOT]
    a = {wt(10), wt(11), aud0, aud1, nullptr, vwt0, vwt1,
         nullptr, nullptr, nullptr, nullptr, nullptr, DD, DD, DD, MTOT, 0, 0, 0};
    mma_gemm<0,2><<<dim3(128, 8, 1), 256, SMEM>>>(a);

    bvWo_kernel<<<DD / 256, 256>>>(bv, Wo, bo, bop);                      // 9

    // 10: scores[b] = Q[b] @ K[b]^T -> fp32
    a = {q0, q1, k0, k1, sc, nullptr, nullptr,
         nullptr, nullptr, nullptr, nullptr, nullptr, DD, DD, DD, SS,
         (long)SS * DD, (long)SS * DD, (long)SS * SS};
    mma_gemm<0,0><<<dim3(16, 16, BB), 256, SMEM>>>(a);
    // 11: softmax -> p splits
    softmax_split<<<MTOT, 256>>>((const float4*)sc, p0, p1);
    // 12: h[b] = P[b] @ VW[b] + bo' + visual[b] -> h splits
    a = {p0, p1, vwt0, vwt1, nullptr, h0, h1,
         bop, nullptr, visual, nullptr, nullptr, SS, SS, MTOT, DD,
         (long)SS * SS, (long)SS, (long)SS * DD};
    mma_gemm<EPI_BIAS|EPI_RES,2><<<dim3(8, 16, BB), 256, SMEM>>>(a);

    wsplitT2z<<<dim3(DD/32, DD/32, 1), 256>>>(W1, W1,
                                              wt(6), wt(7), wt(6), wt(7)); // 13
    init_out<<<MTOT / 256, 256>>>(out, b2);                               // 14
    // 15: x = relu(h @ W1 + b1); out += x . W2 (fused)
    a = {h0, h1, wt(6), wt(7), nullptr, nullptr, nullptr,
         b1, nullptr, nullptr, W2, out, DD, DD, DD, DD, 0, 0, 0};
    mma_gemm<EPI_BIAS|EPI_RELU,3><<<dim3(8, 128, 1), 256, SMEM>>>(a);
}